// round 13
// baseline (speedup 1.0000x reference)
#include <cuda_runtime.h>
#include <math.h>
#include <stdint.h>

#define BB 2
#define CCH 32
#define HH 128
#define WW 128
#define NN (HH*WW)
#define NHEADS 8

// ---------------- scratch (static device globals; no allocation) ----------------
__device__ float g_qkv[BB*96*NN];
__device__ float g_qkvd[BB*96*NN];     // q|k|v after grouped dwconv
__device__ float g_asmall[BB*166*62*62];
__device__ float2 g_offs2[BB*83*NN];   // k4 output: (dy,dx) float2 planes
__device__ float g_catf[BB*96*NN];     // [f3 | f5 | f7]
__device__ float g_kfeat[BB*CCH*NN];
__device__ float g_prompt[BB*CCH*NN];
__device__ float4 g_xnhwc4[BB*NN*8];   // x in NHWC, float4-grouped (16B aligned)
__device__ float g_stage_in[BB*8*24];  // dots[16] | q2[4] | k2[4]
__device__ float g_stage_f[BB*8*44];   // dots[32] | q2[8] | k2[4]
__device__ float g_Meff_in[BB*32*32];
__device__ float g_Meff_f[BB*32*32];

// bf16x2 pair-interleaved staging (u32 = channels (2c, 2c+1))
__device__ uint32_t g_xy16[BB*32*NN];      // cp 0..15 = x, 16..31 = y
__device__ uint32_t g_pool16[BB*32*64*64]; // pooled concat(x,y)
__device__ uint32_t g_bmid16[BB*83*NN];    // k3 output (166 ch -> 83 cp)
__device__ uint32_t g_cat96p16[BB*48*NN];  // [l1 cp0-15 | l2 cp16-31 | xg cp32-47]
__device__ uint32_t g_w16[351360];         // prepacked conv weights (uint2-pair sW image)

// compile-time scratch-buffer resolution
template<int ID> __device__ __forceinline__ float* gbuf();
template<> __device__ __forceinline__ float* gbuf<6>()  { return g_asmall; }
template<> __device__ __forceinline__ float* gbuf<11>() { return g_prompt; }
template<int ID> __device__ __forceinline__ uint32_t* gbufu();
template<> __device__ __forceinline__ uint32_t* gbufu<1>() { return g_xy16; }
template<> __device__ __forceinline__ uint32_t* gbufu<2>() { return g_pool16; }
template<> __device__ __forceinline__ uint32_t* gbufu<3>() { return g_bmid16; }
template<> __device__ __forceinline__ uint32_t* gbufu<4>() { return g_cat96p16; }

// ---------------- bf16 helpers ----------------
__device__ __forceinline__ uint32_t pack_bf16x2(float lo, float hi) {
    uint32_t r;
    asm("cvt.rn.bf16x2.f32 %0, %1, %2;" : "=r"(r) : "f"(hi), "f"(lo));
    return r;
}
__device__ __forceinline__ void mma_bf16(float* d, uint32_t a0, uint32_t a1,
                                         uint32_t a2, uint32_t a3,
                                         uint32_t b0, uint32_t b1) {
    asm volatile("mma.sync.aligned.m16n8k16.row.col.f32.bf16.bf16.f32 "
        "{%0,%1,%2,%3}, {%4,%5,%6,%7}, {%8,%9}, {%0,%1,%2,%3};\n"
        : "+f"(d[0]), "+f"(d[1]), "+f"(d[2]), "+f"(d[3])
        : "r"(a0), "r"(a1), "r"(a2), "r"(a3), "r"(b0), "r"(b1));
}

// ---------------- merged setup ----------------
// blockIdx.y: 0..4 = prepack conv, 5 = pool16 (+stage zero), 6 = pack_xy, 7 = nhwc
// Weight image layout (uint2 pairs): per (octile,chunk) tile of 2592 u32:
//   uint2 idx pi in [0,1296): aoc = pi%36, ck = pi/36, kpos = ck%9, tg = ck/9
//   component comp in {0,1}: cp-row = tg + 4*comp
__global__ void k_setup(const float* __restrict__ x, const float* __restrict__ y,
                        const float* __restrict__ w_lp2, const float* __restrict__ w_c3,
                        const float* __restrict__ w_k2, const float* __restrict__ w_k3,
                        const float* __restrict__ w_k4) {
    __shared__ float s[32][65];
    const int cy = blockIdx.y;
    const int tid0 = blockIdx.x*256 + threadIdx.x;
    const int stride = gridDim.x*256;
    if (cy < 5) {
        const int CINs[5]  = {32, 96, 64, 64, 166};
        const int COUTs[5] = {32, 32, 166, 166, 166};
        const int NCHs[5]  = {2, 6, 4, 4, 11};
        const int OCTs[5]  = {1, 1, 6, 6, 6};
        const int PERMs[5] = {1, 0, 0, 1, 1};
        const int OFFs[5]  = {0, 5184, 20736, 82944, 145152};
        const float* wsv[5] = {w_lp2, w_c3, w_k2, w_k3, w_k4};
        const int CIN = CINs[cy], COUT = COUTs[cy], NCH = NCHs[cy], PERM = PERMs[cy];
        const float* w = wsv[cy];
        const int total = OCTs[cy]*NCH*2592;
        for (int i = tid0; i < total; i += stride) {
            int within = i % 2592;
            int tile   = i / 2592;
            int comp = within & 1;
            int pi   = within >> 1;
            int aoc  = pi % 36;
            int ck   = pi / 36;
            int kpos = ck % 9;
            int tg   = ck / 9;
            int chunk  = tile % NCH;
            int octile = tile / NCH;
            uint32_t val = 0;
            if (aoc < 32) {
                int pc = PERM ? ((aoc & 16) + 2*(aoc & 7) + ((aoc >> 3) & 1)) : aoc;
                int chn = octile*32 + pc;
                int cprow = tg + 4*comp;
                int c0 = chunk*16 + 2*cprow;
                float v0 = 0.f, v1 = 0.f;
                if (chn < COUT && c0 < CIN) {
                    v0 = w[((size_t)chn*CIN + c0)*9 + kpos];
                    v1 = w[((size_t)chn*CIN + c0 + 1)*9 + kpos];
                }
                val = pack_bf16x2(v0, v1);
            }
            g_w16[OFFs[cy] + i] = val;
        }
    } else if (cy == 5) {
        if (blockIdx.x == 0) {
            for (int i = threadIdx.x; i < BB*8*24; i += 256) g_stage_in[i] = 0.f;
            for (int i = threadIdx.x; i < BB*8*44; i += 256) g_stage_f[i] = 0.f;
        }
        for (int gid = tid0; gid < BB*32*4096; gid += stride) {
            int px = gid & 63;
            int py = (gid >> 6) & 63;
            int cp = (gid >> 12) & 31;
            int b  = gid >> 17;
            const float* sp = (cp < 16) ? x + (size_t)(b*32 + 2*cp)*NN
                                        : y + (size_t)(b*32 + 2*(cp-16))*NN;
            int iy = 2*py, ix = 2*px;
            float v0 = 0.25f*(sp[iy*WW+ix] + sp[iy*WW+ix+1] + sp[(iy+1)*WW+ix] + sp[(iy+1)*WW+ix+1]);
            const float* s1 = sp + NN;
            float v1 = 0.25f*(s1[iy*WW+ix] + s1[iy*WW+ix+1] + s1[(iy+1)*WW+ix] + s1[(iy+1)*WW+ix+1]);
            g_pool16[(size_t)(b*32 + cp)*4096 + py*64 + px] = pack_bf16x2(v0, v1);
        }
    } else if (cy == 6) {
        for (int gid = tid0; gid < BB*32*NN; gid += stride) {
            int p = gid % NN;
            int cp = (gid / NN) % 32;
            int b = gid / (32*NN);
            const float* sp = (cp < 16) ? x + (size_t)(b*32 + 2*cp)*NN
                                        : y + (size_t)(b*32 + 2*(cp-16))*NN;
            g_xy16[(size_t)(b*32 + cp)*NN + p] = pack_bf16x2(sp[p], sp[NN + p]);
        }
    } else {
        const int tid = threadIdx.x;
        for (int blk = blockIdx.x; blk < BB*(NN/64); blk += gridDim.x) {
            int b = blk / (NN/64);
            int px0 = (blk % (NN/64)) * 64;
#pragma unroll
            for (int k = 0; k < 8; k++) {
                int ch = k*4 + (tid >> 6);
                int px = tid & 63;
                s[ch][px] = x[(size_t)(b*32 + ch)*NN + px0 + px];
            }
            __syncthreads();
            float* xn = (float*)g_xnhwc4;
#pragma unroll
            for (int k = 0; k < 8; k++) {
                int px = k*8 + (tid >> 5);
                int ch = tid & 31;
                xn[(size_t)(b*NN + px0 + px)*32 + ch] = s[ch][px];
            }
            __syncthreads();
        }
    }
}

// ---------------- conv3x3 body: uint2-paired smem, LDS.64 fragments ----------------
// sIn region: 4256 u32 (4 pairs x 4 rows x 133 uint2); sW region: 2592 u32.
template<int CIN, int COUT, int EPI, int SRCU, int CPTOT, int OUTM, int DSTID,
         int OUTC0, int OUTCTOT, int W16OFF,
         int HIN, int WIN, int HOUT, int WOUT, int PAD>
__device__ __forceinline__ void conv3x3_body(uint32_t* sIn, uint32_t* sW, int bid) {
    constexpr int CP = CIN/2;
    constexpr int NCHUNK = (CP + 7) / 8;
    constexpr int PITCH2 = 133;              // uint2 pitch; 8*133 % 32 = 8 -> conflict-free
    constexpr int ROWS = HOUT/2;
    constexpr int OCT = (COUT + 31)/32;
    const uint32_t* src16 = gbufu<SRCU>();
    const int y0  = (bid % ROWS) * 2;
    const int oc0 = ((bid / ROWS) % OCT) * 32;
    const int b   = bid / (ROWS*OCT);
    const int tid = threadIdx.x;
    const int lane = tid & 31, wid5 = tid >> 5;
    const int wy = wid5 >> 2, wn = wid5 & 3;
    const int g = lane >> 2, tg = lane & 3;

    float acc[2][4][4];
#pragma unroll
    for (int m = 0; m < 2; m++)
#pragma unroll
        for (int t = 0; t < 4; t++)
#pragma unroll
            for (int r = 0; r < 4; r++) acc[m][t][r] = 0.f;

    const uint32_t* wbase = g_w16 + W16OFF + (size_t)(oc0 >> 5)*NCHUNK*2592;

    uint32_t ireg[20];
    uint32_t wreg[11];
    auto load_regs = [&](int ch) {
        int cpg = ch*8 + wid5;
        bool cpv = cpg < CP;
        const uint32_t* sp = src16 + (size_t)(b*CPTOT + cpg)*(HIN*WIN);
#pragma unroll
        for (int row = 0; row < 4; row++) {
            int gy = y0 - PAD + row;
            bool yv = cpv && ((unsigned)gy < (unsigned)HIN);
            const uint32_t* rp = sp + (size_t)gy*WIN;
#pragma unroll
            for (int kk = 0; kk < 5; kk++) {
                int px = lane + 32*kk;
                uint32_t v = 0;
                if (px < PITCH2) {
                    int gx = px - PAD;
                    if (yv && (unsigned)gx < (unsigned)WIN) v = rp[gx];
                }
                ireg[row*5 + kk] = v;
            }
        }
        const uint32_t* wp = wbase + ch*2592;
#pragma unroll
        for (int j = 0; j < 11; j++) {
            int i = tid + j*256;
            wreg[j] = (i < 2592) ? wp[i] : 0u;
        }
    };
    auto store_smem = [&]() {
        int q = wid5 & 3, comp = wid5 >> 2;  // pair q, component (cp-row q + 4*comp)
#pragma unroll
        for (int row = 0; row < 4; row++) {
            uint32_t* sd = sIn + 2*((q*4 + row)*PITCH2) + comp;
#pragma unroll
            for (int kk = 0; kk < 5; kk++) {
                int px = lane + 32*kk;
                if (px < PITCH2) sd[2*px] = ireg[row*5 + kk];
            }
        }
#pragma unroll
        for (int j = 0; j < 11; j++) {
            int i = tid + j*256;
            if (i < 2592) sW[i] = wreg[j];
        }
    };

    load_regs(0);
    store_smem();
    __syncthreads();

    const uint2* sI2 = (const uint2*)sIn;
    const uint2* sW2 = (const uint2*)sW;
    for (int ch = 0; ch < NCHUNK; ch++) {
        if (ch + 1 < NCHUNK) load_regs(ch + 1);
#pragma unroll
        for (int kpos = 0; kpos < 9; kpos++) {
            const int ky = kpos / 3, kx = kpos % 3;
            uint2 A02[2], A13[2];
#pragma unroll
            for (int m = 0; m < 2; m++) {
                const int aoc = m*16 + g;
                A02[m] = sW2[(tg*9 + kpos)*36 + aoc];
                A13[m] = sW2[(tg*9 + kpos)*36 + aoc + 8];
            }
            const int rb = (tg*4 + wy + ky)*PITCH2 + kx;
#pragma unroll
            for (int t = 0; t < 4; t++) {
                int px = wn*32 + t*8 + g;
                uint2 B = sI2[rb + px];
                mma_bf16(acc[0][t], A02[0].x, A13[0].x, A02[0].y, A13[0].y, B.x, B.y);
                mma_bf16(acc[1][t], A02[1].x, A13[1].x, A02[1].y, A13[1].y, B.x, B.y);
            }
        }
        __syncthreads();
        if (ch + 1 < NCHUNK) {
            store_smem();
            __syncthreads();
        }
    }
    const int y = y0 + wy;
#pragma unroll
    for (int m = 0; m < 2; m++) {
        if (OUTM == 1) {
            int chan0 = oc0 + m*16 + 2*g;
            if (chan0 < COUT) {
                uint32_t* op = gbufu<(OUTM == 1) ? DSTID : 1>()
                    + (size_t)(b*OUTCTOT + (OUTC0 + chan0)/2)*(HOUT*WOUT) + (size_t)y*WOUT;
#pragma unroll
                for (int t = 0; t < 4; t++) {
                    int px = wn*32 + t*8 + 2*tg;
                    float v00 = acc[m][t][0], v01 = acc[m][t][1];
                    float v10 = acc[m][t][2], v11 = acc[m][t][3];
                    if (EPI == 2) {
                        int ay = (y * 62) >> 7;
                        int ax0 = (px * 62) >> 7, ax1 = ((px+1) * 62) >> 7;
                        const float* a0p = g_asmall + ((size_t)(b*166 + chan0)*62 + ay)*62;
                        const float* a1p = a0p + 62*62;
                        v00 *= a0p[ax0]; v01 *= a0p[ax1];
                        v10 *= a1p[ax0]; v11 *= a1p[ax1];
                    }
                    op[px]   = pack_bf16x2(v00, v10);
                    op[px+1] = pack_bf16x2(v01, v11);
                }
            }
        } else if (OUTM == 2) {
            int chan0 = oc0 + m*16 + 2*g;
            if (chan0 < COUT) {
                float2* op = g_offs2 + (size_t)(b*83 + chan0/2)*(HOUT*WOUT) + (size_t)y*WOUT;
#pragma unroll
                for (int t = 0; t < 4; t++) {
                    int px = wn*32 + t*8 + 2*tg;
                    op[px]   = make_float2(acc[m][t][0], acc[m][t][2]);
                    op[px+1] = make_float2(acc[m][t][1], acc[m][t][3]);
                }
            }
        } else {
            float* dst = gbuf<(OUTM == 0) ? DSTID : 6>();
            const int ocr0 = oc0 + m*16 + g;
#pragma unroll
            for (int t = 0; t < 4; t++) {
                int px = wn*32 + t*8 + 2*tg;
#pragma unroll
                for (int half = 0; half < 2; half++) {
                    int ocr = ocr0 + half*8;
                    if (ocr >= COUT) continue;
                    float v0 = acc[m][t][half*2 + 0];
                    float v1 = acc[m][t][half*2 + 1];
                    if (EPI == 1) {
                        v0 = 1.f / (1.f + expf(-v0));
                        v1 = 1.f / (1.f + expf(-v1));
                    }
                    float* opf = dst + (size_t)(b*OUTCTOT + OUTC0 + ocr)*(HOUT*WOUT) + (size_t)y*WOUT;
                    if (px   < WOUT) opf[px]   = v0;
                    if (px+1 < WOUT) opf[px+1] = v1;
                }
            }
        }
    }
}

// ---------------- other bodies (unchanged from R12) ----------------
__device__ __forceinline__ void ln_l1_qkv_body(float* sf, int blk,
        const float* __restrict__ x, const float* __restrict__ ln_g,
        const float* __restrict__ ln_b, const float* __restrict__ w_lp1,
        const float* __restrict__ w_qkv) {
    float* sw = sf;
    float* s_g = sf + 1024;
    float* s_b = sf + 1056;
    int tid = threadIdx.x;
    int gid = blk*256 + tid;
    int p = gid % NN;
    int q = (gid / NN) & 3;
    int b = gid / (4*NN);
    const float* wsrc = (q == 0) ? w_lp1 : w_qkv + (size_t)(q-1)*1024;
    for (int i = tid; i < 1024; i += 256) sw[i] = wsrc[i];
    if (tid < 32) { s_g[tid] = ln_g[tid]; s_b[tid] = ln_b[tid]; }
    __syncthreads();
    float xv[32];
#pragma unroll
    for (int c = 0; c < 32; c++) xv[c] = x[(size_t)(b*32 + c)*NN + p];
    if (q == 0) {
#pragma unroll
        for (int m = 0; m < 16; m++) {
            float a0 = 0.f, a1 = 0.f;
#pragma unroll
            for (int c = 0; c < 32; c++) {
                a0 += sw[(2*m)*32 + c]*xv[c];
                a1 += sw[(2*m+1)*32 + c]*xv[c];
            }
            g_cat96p16[(size_t)(b*48 + m)*NN + p] = pack_bf16x2(a0, a1);
        }
    } else {
        float mu = 0.f;
#pragma unroll
        for (int c = 0; c < 32; c++) mu += xv[c];
        mu *= (1.f/32.f);
        float var = 0.f;
#pragma unroll
        for (int c = 0; c < 32; c++) { float d = xv[c]-mu; var += d*d; }
        var *= (1.f/32.f);
        float inv = rsqrtf(var + 1e-5f);
        float vin[32];
#pragma unroll
        for (int c = 0; c < 32; c++) vin[c] = (xv[c]-mu)*inv*s_g[c] + s_b[c];
        float* outbase = g_qkv + (size_t)(b*96 + (q-1)*32)*NN;
        for (int o = 0; o < 32; o++) {
            float a = 0.f;
#pragma unroll
            for (int c = 0; c < 32; c++) a += sw[o*32+c]*vin[c];
            outbase[(size_t)o*NN + p] = a;
        }
    }
}

__device__ __forceinline__ void qkvd_body(float* ws, int blk, const float* __restrict__ w) {
    int tid = threadIdx.x;
    for (int i = tid; i < 96*27; i += 256) ws[i] = w[i];
    __syncthreads();
    int gid = blk*256 + tid;
    int p = gid % NN;
    int g = (gid / NN) % 32;
    int b = gid / (32*NN);
    int y = p >> 7, xx = p & 127;
    float a0 = 0.f, a1 = 0.f, a2 = 0.f;
    const float* inb = g_qkv + (size_t)(b*96 + 3*g)*NN;
#pragma unroll
    for (int ky = 0; ky < 3; ky++) {
        int gy = y - 1 + ky;
        if (gy < 0 || gy >= HH) continue;
#pragma unroll
        for (int kx = 0; kx < 3; kx++) {
            int gx = xx - 1 + kx;
            if (gx < 0 || gx >= WW) continue;
            int kk = ky*3 + kx;
#pragma unroll
            for (int ci = 0; ci < 3; ci++) {
                float v = inb[ci*NN + gy*WW + gx];
                a0 += ws[(3*g+0)*27 + ci*9 + kk]*v;
                a1 += ws[(3*g+1)*27 + ci*9 + kk]*v;
                a2 += ws[(3*g+2)*27 + ci*9 + kk]*v;
            }
        }
    }
    g_qkvd[(size_t)(b*96 + 3*g+0)*NN + p] = a0;
    g_qkvd[(size_t)(b*96 + 3*g+1)*NN + p] = a1;
    g_qkvd[(size_t)(b*96 + 3*g+2)*NN + p] = a2;
}

template<int MODE>
__device__ __forceinline__ void gramacc_body(float* red, int b, int h, int slice,
                                             const float* __restrict__ xin) {
    constexpr int D = (MODE == 0) ? 4 : 8;
    constexpr int E = 4;
    constexpr int NS = D*E + D + E;
    constexpr int SL = 16;
    int tid = threadIdx.x;
    const float* qbase;
    if (MODE == 0) qbase = g_qkvd + (size_t)(b*96 + h*D)*NN;
    else qbase = (h < 4) ? xin + (size_t)(b*32 + h*8)*NN
                         : g_prompt + (size_t)(b*32 + (h-4)*8)*NN;
    const float* kbase = (MODE == 0) ? g_qkvd + (size_t)(b*96 + 32 + h*E)*NN
                                     : g_kfeat + (size_t)(b*32 + h*E)*NN;
    float acc[NS];
#pragma unroll
    for (int i = 0; i < NS; i++) acc[i] = 0.f;
    int n0 = slice * (NN/SL);
    for (int it = 0; it < (NN/SL)/256; it++) {
        int n = n0 + it*256 + tid;
        float qv[D], kv[E];
#pragma unroll
        for (int d = 0; d < D; d++) qv[d] = qbase[(size_t)d*NN + n];
#pragma unroll
        for (int e = 0; e < E; e++) kv[e] = kbase[(size_t)e*NN + n];
#pragma unroll
        for (int d = 0; d < D; d++)
#pragma unroll
            for (int e = 0; e < E; e++) acc[d*E+e] += qv[d]*kv[e];
#pragma unroll
        for (int d = 0; d < D; d++) acc[D*E + d] += qv[d]*qv[d];
#pragma unroll
        for (int e = 0; e < E; e++) acc[D*E + D + e] += kv[e]*kv[e];
    }
    if (tid < NS) red[tid] = 0.f;
    __syncthreads();
    int lane = tid & 31;
#pragma unroll
    for (int i = 0; i < NS; i++) {
        float v = acc[i];
#pragma unroll
        for (int o = 16; o > 0; o >>= 1) v += __shfl_down_sync(0xffffffffu, v, o);
        if (lane == 0) atomicAdd(&red[i], v);
    }
    __syncthreads();
    float* st = (MODE == 0) ? g_stage_in + (b*8 + h)*24 : g_stage_f + (b*8 + h)*44;
    if (tid < NS) atomicAdd(&st[tid], red[tid]);
}

__device__ __forceinline__ void meffsm0_body(float* sA, int b,
        const float* __restrict__ wmat, const float* __restrict__ tempv) {
    int t = threadIdx.x;
    if (t < 32) {
        int h = t >> 2, d = t & 3;
        const float* st = g_stage_in + (b*8 + h)*24;
        float qn = fmaxf(sqrtf(st[16 + d]), 1e-12f);
        float tp = tempv[h];
        float row[4];
        float mx = -1e30f;
#pragma unroll
        for (int e = 0; e < 4; e++) {
            float kn = fmaxf(sqrtf(st[20 + e]), 1e-12f);
            row[e] = st[d*4+e] / (qn*kn) * tp;
            mx = fmaxf(mx, row[e]);
        }
        float sum = 0.f;
#pragma unroll
        for (int e = 0; e < 4; e++) { row[e] = expf(row[e]-mx); sum += row[e]; }
        float isum = 1.f/sum;
#pragma unroll
        for (int e = 0; e < 4; e++) sA[(h*4 + d)*4 + e] = row[e]*isum;
    }
    __syncthreads();
#pragma unroll
    for (int r = 0; r < 4; r++) {
        int idx = r*256 + t;
        int o = idx >> 5, vc = idx & 31, h = vc >> 2, e = vc & 3;
        float s = 0.f;
#pragma unroll
        for (int d = 0; d < 4; d++)
            s += wmat[o*32 + h*4 + d] * sA[(h*4 + d)*4 + e];
        g_Meff_in[b*1024 + o*32 + vc] = s;
    }
}

__global__ void k_meffsm1(const float* __restrict__ wmat, const float* __restrict__ tempv) {
    constexpr int D = 8;
    int b = blockIdx.x;
    int t = threadIdx.x;
    __shared__ float sA[8*D*4];
    if (t < 8*D) {
        int h = t / D, d = t % D;
        const float* st = g_stage_f + (b*8 + h)*44;
        float qn = fmaxf(sqrtf(st[D*4 + d]), 1e-12f);
        float tp = tempv[h];
        float row[4];
        float mx = -1e30f;
#pragma unroll
        for (int e = 0; e < 4; e++) {
            float kn = fmaxf(sqrtf(st[D*4 + D + e]), 1e-12f);
            row[e] = st[d*4+e] / (qn*kn) * tp;
            mx = fmaxf(mx, row[e]);
        }
        float sum = 0.f;
#pragma unroll
        for (int e = 0; e < 4; e++) { row[e] = expf(row[e]-mx); sum += row[e]; }
        float isum = 1.f/sum;
#pragma unroll
        for (int e = 0; e < 4; e++) sA[(h*D + d)*4 + e] = row[e]*isum;
    }
    __syncthreads();
    int o = t >> 5, vc = t & 31, h = vc >> 2, e = vc & 3;
    float s = 0.f;
#pragma unroll
    for (int d = 0; d < D; d++)
        s += wmat[o*(8*D) + h*D + d] * sA[(h*D + d)*4 + e];
    g_Meff_f[b*1024 + o*32 + vc] = s;
}

template<int MODE>
__device__ __forceinline__ void apply_body(float* sm, int blk,
        const float* __restrict__ xin, float* __restrict__ outp) {
    int tid = threadIdx.x;
    int gid = blk*256 + tid;
    int p = gid % NN;
    int q = (gid / NN) & 3;
    int b = gid / (4*NN);
    const float* M = (MODE == 0) ? g_Meff_in : g_Meff_f;
    if (tid < 256) sm[tid] = M[b*1024 + q*256 + tid];
    __syncthreads();
    float vv[32];
#pragma unroll
    for (int c = 0; c < 32; c++) {
        if (MODE == 0) vv[c] = g_qkvd[(size_t)(b*96 + 64 + c)*NN + p];
        else           vv[c] = xin[(size_t)(b*32 + c)*NN + p];
    }
    float av[8];
#pragma unroll
    for (int j = 0; j < 8; j++) {
        int o = q*8 + j;
        float a = (MODE == 0) ? xin[(size_t)(b*32 + o)*NN + p] : 0.f;
#pragma unroll
        for (int c = 0; c < 32; c++) a += sm[j*32+c]*vv[c];
        av[j] = a;
    }
    if (MODE == 0) {
#pragma unroll
        for (int m = 0; m < 4; m++)
            g_cat96p16[(size_t)(b*48 + 32 + q*4 + m)*NN + p] = pack_bf16x2(av[2*m], av[2*m+1]);
    } else {
#pragma unroll
        for (int j = 0; j < 8; j++)
            outp[(size_t)(b*32 + q*8 + j)*NN + p] = av[j];
    }
}

template<int K, int PAD>
__device__ __forceinline__ void deform_one(const float2* __restrict__ offp,
                                           const float* __restrict__ ws,
                                           const float* __restrict__ bsh,
                                           int yy, int xx, int b, int g, int p,
                                           int out0) {
    constexpr int K2 = K*K;
    float acc0 = 0.f, acc1 = 0.f, acc2 = 0.f, acc3 = 0.f;
    const float4* xb = g_xnhwc4 + (size_t)b*NN*8 + g;
    for (int k2 = 0; k2 < K2; k2++) {
        float2 d = offp[(size_t)k2*NN];
        float py = (float)(yy - PAD + k2 / K) + d.x;
        float px = (float)(xx - PAD + k2 % K) + d.y;
        float y0f = floorf(py), x0f = floorf(px);
        float wy = py - y0f, wx = px - x0f;
        int y0 = (int)y0f, x0 = (int)x0f;
        float w00 = (1.f-wy)*(1.f-wx), w01 = (1.f-wy)*wx, w10 = wy*(1.f-wx), w11 = wy*wx;
        bool iy0 = (y0 >= 0 && y0 < HH), iy1 = (y0+1 >= 0 && y0+1 < HH);
        bool ix0 = (x0 >= 0 && x0 < WW), ix1 = (x0+1 >= 0 && x0+1 < WW);
        float4 s = make_float4(0.f, 0.f, 0.f, 0.f);
        if (iy0 && ix0) {
            float4 v = xb[(size_t)(y0*WW + x0)*8];
            s.x += w00*v.x; s.y += w00*v.y; s.z += w00*v.z; s.w += w00*v.w;
        }
        if (iy0 && ix1) {
            float4 v = xb[(size_t)(y0*WW + x0 + 1)*8];
            s.x += w01*v.x; s.y += w01*v.y; s.z += w01*v.z; s.w += w01*v.w;
        }
        if (iy1 && ix0) {
            float4 v = xb[(size_t)((y0+1)*WW + x0)*8];
            s.x += w10*v.x; s.y += w10*v.y; s.z += w10*v.z; s.w += w10*v.w;
        }
        if (iy1 && ix1) {
            float4 v = xb[(size_t)((y0+1)*WW + x0 + 1)*8];
            s.x += w11*v.x; s.y += w11*v.y; s.z += w11*v.z; s.w += w11*v.w;
        }
        acc0 += ws[(0*4+0)*K2+k2]*s.x + ws[(0*4+1)*K2+k2]*s.y + ws[(0*4+2)*K2+k2]*s.z + ws[(0*4+3)*K2+k2]*s.w;
        acc1 += ws[(1*4+0)*K2+k2]*s.x + ws[(1*4+1)*K2+k2]*s.y + ws[(1*4+2)*K2+k2]*s.z + ws[(1*4+3)*K2+k2]*s.w;
        acc2 += ws[(2*4+0)*K2+k2]*s.x + ws[(2*4+1)*K2+k2]*s.y + ws[(2*4+2)*K2+k2]*s.z + ws[(2*4+3)*K2+k2]*s.w;
        acc3 += ws[(3*4+0)*K2+k2]*s.x + ws[(3*4+1)*K2+k2]*s.y + ws[(3*4+2)*K2+k2]*s.z + ws[(3*4+3)*K2+k2]*s.w;
    }
    float* ob = g_catf + (size_t)(b*96 + out0 + g*4)*NN + p;
    ob[0*NN] = fmaxf(acc0 + bsh[0], 0.f);
    ob[1*NN] = fmaxf(acc1 + bsh[1], 0.f);
    ob[2*NN] = fmaxf(acc2 + bsh[2], 0.f);
    ob[3*NN] = fmaxf(acc3 + bsh[3], 0.f);
}

__device__ __forceinline__ void deform_all_body(float* ws, int blk,
        const float* __restrict__ w3, const float* __restrict__ b3,
        const float* __restrict__ w5, const float* __restrict__ b5,
        const float* __restrict__ w7, const float* __restrict__ b7) {
    float* bsh = ws + 1328;
    int tid = threadIdx.x;
    int gid = blk*256 + tid;
    int p = gid % NN;
    int g = (gid / NN) & 7;
    int b = gid / (8*NN);
    for (int i = tid; i < 144; i += 256) ws[i] = w3[g*144 + i];
    for (int i = tid; i < 400; i += 256) ws[144 + i] = w5[g*400 + i];
    for (int i = tid; i < 784; i += 256) ws[544 + i] = w7[g*784 + i];
    if (tid < 4)       bsh[tid] = b3[g*4 + tid];
    else if (tid < 8)  bsh[tid] = b5[g*4 + tid - 4];
    else if (tid < 12) bsh[tid] = b7[g*4 + tid - 8];
    __syncthreads();
    int yy = p >> 7, xx = p & 127;
    const float2* offbase = g_offs2 + (size_t)(b*83)*NN + p;
    deform_one<3,1>(offbase,                 ws,     bsh,    yy, xx, b, g, p, 0);
    deform_one<5,2>(offbase + (size_t)9*NN,  ws+144, bsh+4,  yy, xx, b, g, p, 32);
    deform_one<7,3>(offbase + (size_t)34*NN, ws+544, bsh+8,  yy, xx, b, g, p, 64);
}

__device__ __forceinline__ void pw_body(float* ws, int blk,
        const float* __restrict__ w, const float* __restrict__ bias) {
    float* bs = ws + 768;
    int tid = threadIdx.x;
    int gid = blk*256 + tid;
    int p = gid % NN;
    int q = (gid / NN) & 3;
    int b = gid / (4*NN);
    for (int i = tid; i < 768; i += 256) ws[i] = w[(size_t)(q*8 + i/96)*96 + i%96];
    if (tid < 8) bs[tid] = bias[q*8 + tid];
    __syncthreads();
    float acc[8];
#pragma unroll
    for (int j = 0; j < 8; j++) acc[j] = bs[j];
    for (int c = 0; c < 96; c++) {
        float v = g_catf[(size_t)(b*96 + c)*NN + p];
#pragma unroll
        for (int j = 0; j < 8; j++) acc[j] += ws[j*96 + c]*v;
    }
#pragma unroll
    for (int j = 0; j < 8; j++) g_kfeat[(size_t)(b*32 + q*8 + j)*NN + p] = acc[j];
}

// ---------------- merged launch wrappers ----------------
// M1: [0,372) k2conv | [372,884) ln_l1_qkv | [884,1012) l2conv
__global__ void __launch_bounds__(256, 2) k_m1(const float* __restrict__ x,
        const float* __restrict__ ln_g, const float* __restrict__ ln_b,
        const float* __restrict__ w_lp1, const float* __restrict__ w_qkv) {
    __shared__ __align__(16) uint32_t sbuf[6848];
    int bid = blockIdx.x;
    if (bid < 372) {
        conv3x3_body<64,166,1, 2,32, 0,6, 0,166, 20736, 64,64,62,62, 0>(sbuf, sbuf + 4256, bid);
    } else if (bid < 884) {
        ln_l1_qkv_body((float*)sbuf, bid - 372, x, ln_g, ln_b, w_lp1, w_qkv);
    } else {
        conv3x3_body<32,32,0, 1,32, 1,4, 32,48, 0, 128,128,128,128, 1>(sbuf, sbuf + 4256, bid - 884);
    }
}

// M2: [0,768) k3conv | [768,1792) qkvd
__global__ void __launch_bounds__(256, 2) k_m2(const float* __restrict__ w_qkvd) {
    __shared__ __align__(16) uint32_t sbuf[6848];
    int bid = blockIdx.x;
    if (bid < 768) {
        conv3x3_body<64,166,2, 1,32, 1,3, 0,83, 82944, 128,128,128,128, 1>(sbuf, sbuf + 4256, bid);
    } else {
        qkvd_body((float*)sbuf, bid - 768, w_qkvd);
    }
}

// M3: [0,768) k4conv | [768,1024) gramacc0
__global__ void __launch_bounds__(256, 2) k_m3(const float* __restrict__ x) {
    __shared__ __align__(16) uint32_t sbuf[6848];
    int bid = blockIdx.x;
    if (bid < 768) {
        conv3x3_body<166,166,0, 3,83, 2,6, 0,83, 145152, 128,128,128,128, 1>(sbuf, sbuf + 4256, bid);
    } else {
        int i = bid - 768;
        gramacc_body<0>((float*)sbuf, i >> 7, (i >> 4) & 7, i & 15, x);
    }
}

// M4: [0,1024) deform | [1024,1026) meffsm0
__global__ void k_m4(const float* __restrict__ w3, const float* __restrict__ b3,
                     const float* __restrict__ w5, const float* __restrict__ b5,
                     const float* __restrict__ w7, const float* __restrict__ b7,
                     const float* __restrict__ w_mproj, const float* __restrict__ temp_in) {
    __shared__ float sf[1344];
    int bid = blockIdx.x;
    if (bid < 1024) {
        deform_all_body(sf, bid, w3, b3, w5, b5, w7, b7);
    } else {
        meffsm0_body(sf, bid - 1024, w_mproj, temp_in);
    }
}

// M5: [0,512) pw | [512,1024) apply0
__global__ void k_m5(const float* __restrict__ w_pw, const float* __restrict__ b_pw,
                     const float* __restrict__ x) {
    __shared__ float sf[800];
    int bid = blockIdx.x;
    if (bid < 512) {
        pw_body(sf, bid, w_pw, b_pw);
    } else {
        apply_body<0>(sf, bid - 512, x, nullptr);
    }
}

// M6: [0,128) c3conv | [128,256) gramacc1 with h<4 (x-half)
__global__ void __launch_bounds__(256, 2) k_m6(const float* __restrict__ x) {
    __shared__ __align__(16) uint32_t sbuf[6848];
    int bid = blockIdx.x;
    if (bid < 128) {
        conv3x3_body<96,32,0, 4,48, 0,11, 0,32, 5184, 128,128,128,128, 1>(sbuf, sbuf + 4256, bid);
    } else {
        int i = bid - 128;
        gramacc_body<1>((float*)sbuf, i >> 6, (i >> 4) & 3, i & 15, x);
    }
}

// M7: gramacc1 with h>=4 (prompt-half)
__global__ void k_m7(const float* __restrict__ x) {
    __shared__ float sf[64];
    int i = blockIdx.x;
    gramacc_body<1>(sf, i >> 6, 4 + ((i >> 4) & 3), i & 15, x);
}

// final apply
__global__ void k_apply1(const float* __restrict__ x, float* __restrict__ outp) {
    __shared__ float sf[256];
    apply_body<1>(sf, blockIdx.x, x, outp);
}

// ---------------- launch (kernel launches ONLY) ----------------
extern "C" void kernel_launch(void* const* d_in, const int* in_sizes, int n_in,
                              void* d_out, int out_size) {
    const float* x       = (const float*)d_in[0];
    const float* y       = (const float*)d_in[1];
    const float* temp    = (const float*)d_in[2];
    const float* w_po    = (const float*)d_in[3];
    const float* w_lp1   = (const float*)d_in[4];
    const float* w_lp2   = (const float*)d_in[5];
    const float* ln_g    = (const float*)d_in[6];
    const float* ln_b    = (const float*)d_in[7];
    const float* temp_in = (const float*)d_in[8];
    const float* w_qkv   = (const float*)d_in[9];
    const float* w_qkvd  = (const float*)d_in[10];
    const float* w_mproj = (const float*)d_in[11];
    const float* w_c3    = (const float*)d_in[12];
    const float* w_k2    = (const float*)d_in[13];
    const float* w_k3    = (const float*)d_in[14];
    const float* w_k4    = (const float*)d_in[15];
    const float* w_d3    = (const float*)d_in[16];
    const float* b_d3    = (const float*)d_in[17];
    const float* w_d5    = (const float*)d_in[18];
    const float* b_d5    = (const float*)d_in[19];
    const float* w_d7    = (const float*)d_in[20];
    const float* b_d7    = (const float*)d_in[21];
    const float* w_pw    = (const float*)d_in[22];
    const float* b_pw    = (const float*)d_in[23];

    k_setup<<<dim3(256, 8), 256>>>(x, y, w_lp2, w_c3, w_k2, w_k3, w_k4);  // 0
    k_m1<<<1012, 256>>>(x, ln_g, ln_b, w_lp1, w_qkv);                      // 1: k2 | ln+l1+qkv | l2
    k_m2<<<1792, 256>>>(w_qkvd);                                           // 2: k3 | qkvd
    k_m3<<<1024, 256>>>(x);                                                // 3: k4 | gramacc0  <- profiled
    k_m4<<<1026, 256>>>(w_d3, b_d3, w_d5, b_d5, w_d7, b_d7, w_mproj, temp_in); // 4
    k_m5<<<1024, 256>>>(w_pw, b_pw, x);                                    // 5: pw | apply0
    k_m6<<<256, 256>>>(x);                                                 // 6: c3 | gramacc1(h<4)
    k_m7<<<128, 256>>>(x);                                                 // 7: gramacc1(h>=4)
    k_meffsm1<<<BB, 1024>>>(w_po, temp);                                   // 8
    k_apply1<<<(BB*4*NN)/256, 256>>>(x, (float*)d_out);                    // 9
}

// round 15
// speedup vs baseline: 1.0559x; 1.0559x over previous
#include <cuda_runtime.h>
#include <math.h>
#include <stdint.h>

#define BB 2
#define CCH 32
#define HH 128
#define WW 128
#define NN (HH*WW)
#define NHEADS 8

// ---------------- scratch (static device globals; no allocation) ----------------
__device__ float g_qkv[BB*96*NN];
__device__ float g_qkvd[BB*96*NN];     // q|k|v after grouped dwconv
__device__ float g_asmall[BB*166*62*62];
__device__ float2 g_offs2[BB*83*NN];   // k4 output: (dy,dx) float2 planes
__device__ float g_catf[BB*96*NN];     // [f3 | f5 | f7]
__device__ float g_kfeat[BB*CCH*NN];
__device__ float g_prompt[BB*CCH*NN];
__device__ float4 g_xnhwc4[BB*NN*8];   // x in NHWC, float4-grouped (16B aligned)
__device__ float g_stage_in[BB*8*24];  // dots[16] | q2[4] | k2[4]
__device__ float g_stage_f[BB*8*44];   // dots[32] | q2[8] | k2[4]
__device__ float g_Meff_in[BB*32*32];
__device__ float g_Meff_f[BB*32*32];

// bf16x2 pair-interleaved staging (u32 = channels (2c, 2c+1))
__device__ uint32_t g_xy16[BB*32*NN];      // cp 0..15 = x, 16..31 = y
__device__ uint32_t g_pool16[BB*32*64*64]; // pooled concat(x,y)
__device__ uint32_t g_bmid16[BB*83*NN];    // k3 output (166 ch -> 83 cp)
__device__ uint32_t g_cat96p16[BB*48*NN];  // [l1 cp0-15 | l2 cp16-31 | xg cp32-47]
__device__ uint32_t g_w16[351360];         // prepacked conv weights (sW image, pitch 40)

// compile-time scratch-buffer resolution
template<int ID> __device__ __forceinline__ float* gbuf();
template<> __device__ __forceinline__ float* gbuf<6>()  { return g_asmall; }
template<> __device__ __forceinline__ float* gbuf<11>() { return g_prompt; }
template<int ID> __device__ __forceinline__ uint32_t* gbufu();
template<> __device__ __forceinline__ uint32_t* gbufu<1>() { return g_xy16; }
template<> __device__ __forceinline__ uint32_t* gbufu<2>() { return g_pool16; }
template<> __device__ __forceinline__ uint32_t* gbufu<3>() { return g_bmid16; }
template<> __device__ __forceinline__ uint32_t* gbufu<4>() { return g_cat96p16; }

// ---------------- bf16 helpers ----------------
__device__ __forceinline__ uint32_t pack_bf16x2(float lo, float hi) {
    uint32_t r;
    asm("cvt.rn.bf16x2.f32 %0, %1, %2;" : "=r"(r) : "f"(hi), "f"(lo));
    return r;
}
__device__ __forceinline__ void mma_bf16(float* d, uint32_t a0, uint32_t a1,
                                         uint32_t a2, uint32_t a3,
                                         uint32_t b0, uint32_t b1) {
    asm volatile("mma.sync.aligned.m16n8k16.row.col.f32.bf16.bf16.f32 "
        "{%0,%1,%2,%3}, {%4,%5,%6,%7}, {%8,%9}, {%0,%1,%2,%3};\n"
        : "+f"(d[0]), "+f"(d[1]), "+f"(d[2]), "+f"(d[3])
        : "r"(a0), "r"(a1), "r"(a2), "r"(a3), "r"(b0), "r"(b1));
}

// ---------------- merged setup ----------------
// blockIdx.y: 0..4 = prepack conv, 5 = pool16 (+stage zero), 6 = pack_xy, 7 = nhwc
__global__ void k_setup(const float* __restrict__ x, const float* __restrict__ y,
                        const float* __restrict__ w_lp2, const float* __restrict__ w_c3,
                        const float* __restrict__ w_k2, const float* __restrict__ w_k3,
                        const float* __restrict__ w_k4) {
    __shared__ float s[32][65];
    const int cy = blockIdx.y;
    const int tid0 = blockIdx.x*256 + threadIdx.x;
    const int stride = gridDim.x*256;
    if (cy < 5) {
        const int CINs[5]  = {32, 96, 64, 64, 166};
        const int COUTs[5] = {32, 32, 166, 166, 166};
        const int NCHs[5]  = {2, 6, 4, 4, 11};
        const int OCTs[5]  = {1, 1, 6, 6, 6};
        const int PERMs[5] = {1, 0, 0, 1, 1};
        const int OFFs[5]  = {0, 5760, 23040, 92160, 161280};
        const float* wsv[5] = {w_lp2, w_c3, w_k2, w_k3, w_k4};
        const int CIN = CINs[cy], COUT = COUTs[cy], NCH = NCHs[cy], PERM = PERMs[cy];
        const float* w = wsv[cy];
        const int total = OCTs[cy]*NCH*2880;
        for (int i = tid0; i < total; i += stride) {
            int within = i % 2880;
            int tile   = i / 2880;
            int oc = within % 40;
            int ck = within / 40;
            int k  = ck % 9;
            int cp = ck / 9;
            int chunk  = tile % NCH;
            int octile = tile / NCH;
            uint32_t val = 0;
            if (oc < 32) {
                int pc = PERM ? ((oc & 16) + 2*(oc & 7) + ((oc >> 3) & 1)) : oc;
                int chn = octile*32 + pc;
                int c0 = chunk*16 + 2*cp;
                float v0 = 0.f, v1 = 0.f;
                if (chn < COUT && c0 < CIN) {
                    v0 = w[((size_t)chn*CIN + c0)*9 + k];
                    v1 = w[((size_t)chn*CIN + c0 + 1)*9 + k];
                }
                val = pack_bf16x2(v0, v1);
            }
            g_w16[OFFs[cy] + i] = val;
        }
    } else if (cy == 5) {
        if (blockIdx.x == 0) {
            for (int i = threadIdx.x; i < BB*8*24; i += 256) g_stage_in[i] = 0.f;
            for (int i = threadIdx.x; i < BB*8*44; i += 256) g_stage_f[i] = 0.f;
        }
        for (int gid = tid0; gid < BB*32*4096; gid += stride) {
            int px = gid & 63;
            int py = (gid >> 6) & 63;
            int cp = (gid >> 12) & 31;
            int b  = gid >> 17;
            const float* sp = (cp < 16) ? x + (size_t)(b*32 + 2*cp)*NN
                                        : y + (size_t)(b*32 + 2*(cp-16))*NN;
            int iy = 2*py, ix = 2*px;
            float v0 = 0.25f*(sp[iy*WW+ix] + sp[iy*WW+ix+1] + sp[(iy+1)*WW+ix] + sp[(iy+1)*WW+ix+1]);
            const float* s1 = sp + NN;
            float v1 = 0.25f*(s1[iy*WW+ix] + s1[iy*WW+ix+1] + s1[(iy+1)*WW+ix] + s1[(iy+1)*WW+ix+1]);
            g_pool16[(size_t)(b*32 + cp)*4096 + py*64 + px] = pack_bf16x2(v0, v1);
        }
    } else if (cy == 6) {
        for (int gid = tid0; gid < BB*32*NN; gid += stride) {
            int p = gid % NN;
            int cp = (gid / NN) % 32;
            int b = gid / (32*NN);
            const float* sp = (cp < 16) ? x + (size_t)(b*32 + 2*cp)*NN
                                        : y + (size_t)(b*32 + 2*(cp-16))*NN;
            g_xy16[(size_t)(b*32 + cp)*NN + p] = pack_bf16x2(sp[p], sp[NN + p]);
        }
    } else {
        const int tid = threadIdx.x;
        for (int blk = blockIdx.x; blk < BB*(NN/64); blk += gridDim.x) {
            int b = blk / (NN/64);
            int px0 = (blk % (NN/64)) * 64;
#pragma unroll
            for (int k = 0; k < 8; k++) {
                int ch = k*4 + (tid >> 6);
                int px = tid & 63;
                s[ch][px] = x[(size_t)(b*32 + ch)*NN + px0 + px];
            }
            __syncthreads();
            float* xn = (float*)g_xnhwc4;
#pragma unroll
            for (int k = 0; k < 8; k++) {
                int px = k*8 + (tid >> 5);
                int ch = tid & 31;
                xn[(size_t)(b*NN + px0 + px)*32 + ch] = s[ch][px];
            }
            __syncthreads();
        }
    }
}

// ---------------- conv3x3 body (R12 layout; uint4 weight copy) ----------------
template<int CIN, int COUT, int EPI, int SRCU, int CPTOT, int OUTM, int DSTID,
         int OUTC0, int OUTCTOT, int W16OFF,
         int HIN, int WIN, int HOUT, int WOUT, int PAD>
__device__ __forceinline__ void conv3x3_body(uint32_t* sIn, uint32_t* sW, int bid) {
    constexpr int CP = CIN/2;
    constexpr int NCHUNK = (CP + 7) / 8;
    constexpr int PITCH = 134;
    constexpr int ROWS = HOUT/2;
    constexpr int OCT = (COUT + 31)/32;
    const uint32_t* src16 = gbufu<SRCU>();
    const int y0  = (bid % ROWS) * 2;
    const int oc0 = ((bid / ROWS) % OCT) * 32;
    const int b   = bid / (ROWS*OCT);
    const int tid = threadIdx.x;
    const int lane = tid & 31, wid5 = tid >> 5;
    const int wy = wid5 >> 2, wn = wid5 & 3;
    const int g = lane >> 2, tg = lane & 3;

    float acc[2][4][4];
#pragma unroll
    for (int m = 0; m < 2; m++)
#pragma unroll
        for (int t = 0; t < 4; t++)
#pragma unroll
            for (int r = 0; r < 4; r++) acc[m][t][r] = 0.f;

    const uint32_t* wbase = g_w16 + W16OFF + (size_t)(oc0 >> 5)*NCHUNK*2880;

    uint32_t ireg[20];
    uint4 wreg4[3];
    auto load_regs = [&](int ch) {
        int cpg = ch*8 + wid5;
        bool cpv = cpg < CP;
        const uint32_t* sp = src16 + (size_t)(b*CPTOT + cpg)*(HIN*WIN);
#pragma unroll
        for (int row = 0; row < 4; row++) {
            int gy = y0 - PAD + row;
            bool yv = cpv && ((unsigned)gy < (unsigned)HIN);
            const uint32_t* rp = sp + (size_t)gy*WIN;
#pragma unroll
            for (int kk = 0; kk < 5; kk++) {
                int px = lane + 32*kk;
                uint32_t v = 0;
                if (px < PITCH) {
                    int gx = px - PAD;
                    if (yv && (unsigned)gx < (unsigned)WIN) v = rp[gx];
                }
                ireg[row*5 + kk] = v;
            }
        }
        const uint4* wp4 = (const uint4*)(wbase + ch*2880);   // 16B-aligned (offsets % 4 == 0)
#pragma unroll
        for (int j = 0; j < 3; j++) {
            int i = tid + j*256;
            if (i < 720) wreg4[j] = wp4[i];
        }
    };
    auto store_smem = [&]() {
#pragma unroll
        for (int row = 0; row < 4; row++) {
            uint32_t* sd = sIn + (wid5*4 + row)*PITCH;
#pragma unroll
            for (int kk = 0; kk < 5; kk++) {
                int px = lane + 32*kk;
                if (px < PITCH) sd[px] = ireg[row*5 + kk];
            }
        }
        uint4* sW4 = (uint4*)sW;
#pragma unroll
        for (int j = 0; j < 3; j++) {
            int i = tid + j*256;
            if (i < 720) sW4[i] = wreg4[j];
        }
    };

    load_regs(0);
    store_smem();
    __syncthreads();

    for (int ch = 0; ch < NCHUNK; ch++) {
        if (ch + 1 < NCHUNK) load_regs(ch + 1);
#pragma unroll
        for (int kpos = 0; kpos < 9; kpos++) {
            const int ky = kpos / 3, kx = kpos % 3;
            uint32_t a[2][4];
#pragma unroll
            for (int m = 0; m < 2; m++) {
                const int aoc = m*16 + g;
                a[m][0] = sW[(tg*9 + kpos)*40 + aoc];
                a[m][1] = sW[(tg*9 + kpos)*40 + aoc + 8];
                a[m][2] = sW[((tg+4)*9 + kpos)*40 + aoc];
                a[m][3] = sW[((tg+4)*9 + kpos)*40 + aoc + 8];
            }
            const int r0 = (tg*4 + wy + ky)*PITCH + kx;
            const int r1 = ((tg+4)*4 + wy + ky)*PITCH + kx;
#pragma unroll
            for (int t = 0; t < 4; t++) {
                int px = wn*32 + t*8 + g;
                uint32_t b0 = sIn[r0 + px], b1 = sIn[r1 + px];
                mma_bf16(acc[0][t], a[0][0], a[0][1], a[0][2], a[0][3], b0, b1);
                mma_bf16(acc[1][t], a[1][0], a[1][1], a[1][2], a[1][3], b0, b1);
            }
        }
        __syncthreads();
        if (ch + 1 < NCHUNK) {
            store_smem();
            __syncthreads();
        }
    }
    const int y = y0 + wy;
#pragma unroll
    for (int m = 0; m < 2; m++) {
        if (OUTM == 1) {
            int chan0 = oc0 + m*16 + 2*g;
            if (chan0 < COUT) {
                uint32_t* op = gbufu<(OUTM == 1) ? DSTID : 1>()
                    + (size_t)(b*OUTCTOT + (OUTC0 + chan0)/2)*(HOUT*WOUT) + (size_t)y*WOUT;
#pragma unroll
                for (int t = 0; t < 4; t++) {
                    int px = wn*32 + t*8 + 2*tg;
                    float v00 = acc[m][t][0], v01 = acc[m][t][1];
                    float v10 = acc[m][t][2], v11 = acc[m][t][3];
                    if (EPI == 2) {
                        int ay = (y * 62) >> 7;
                        int ax0 = (px * 62) >> 7, ax1 = ((px+1) * 62) >> 7;
                        const float* a0p = g_asmall + ((size_t)(b*166 + chan0)*62 + ay)*62;
                        const float* a1p = a0p + 62*62;
                        v00 *= a0p[ax0]; v01 *= a0p[ax1];
                        v10 *= a1p[ax0]; v11 *= a1p[ax1];
                    }
                    op[px]   = pack_bf16x2(v00, v10);
                    op[px+1] = pack_bf16x2(v01, v11);
                }
            }
        } else if (OUTM == 2) {
            int chan0 = oc0 + m*16 + 2*g;
            if (chan0 < COUT) {
                float2* op = g_offs2 + (size_t)(b*83 + chan0/2)*(HOUT*WOUT) + (size_t)y*WOUT;
#pragma unroll
                for (int t = 0; t < 4; t++) {
                    int px = wn*32 + t*8 + 2*tg;
                    op[px]   = make_float2(acc[m][t][0], acc[m][t][2]);
                    op[px+1] = make_float2(acc[m][t][1], acc[m][t][3]);
                }
            }
        } else {
            float* dst = gbuf<(OUTM == 0) ? DSTID : 6>();
            const int ocr0 = oc0 + m*16 + g;
#pragma unroll
            for (int t = 0; t < 4; t++) {
                int px = wn*32 + t*8 + 2*tg;
#pragma unroll
                for (int half = 0; half < 2; half++) {
                    int ocr = ocr0 + half*8;
                    if (ocr >= COUT) continue;
                    float v0 = acc[m][t][half*2 + 0];
                    float v1 = acc[m][t][half*2 + 1];
                    if (EPI == 1) {
                        v0 = 1.f / (1.f + expf(-v0));
                        v1 = 1.f / (1.f + expf(-v1));
                    }
                    float* opf = dst + (size_t)(b*OUTCTOT + OUTC0 + ocr)*(HOUT*WOUT) + (size_t)y*WOUT;
                    if (px   < WOUT) opf[px]   = v0;
                    if (px+1 < WOUT) opf[px+1] = v1;
                }
            }
        }
    }
}

// ---------------- other bodies (unchanged from R12) ----------------
__device__ __forceinline__ void ln_l1_qkv_body(float* sf, int blk,
        const float* __restrict__ x, const float* __restrict__ ln_g,
        const float* __restrict__ ln_b, const float* __restrict__ w_lp1,
        const float* __restrict__ w_qkv) {
    float* sw = sf;
    float* s_g = sf + 1024;
    float* s_b = sf + 1056;
    int tid = threadIdx.x;
    int gid = blk*256 + tid;
    int p = gid % NN;
    int q = (gid / NN) & 3;
    int b = gid / (4*NN);
    const float* wsrc = (q == 0) ? w_lp1 : w_qkv + (size_t)(q-1)*1024;
    for (int i = tid; i < 1024; i += 256) sw[i] = wsrc[i];
    if (tid < 32) { s_g[tid] = ln_g[tid]; s_b[tid] = ln_b[tid]; }
    __syncthreads();
    float xv[32];
#pragma unroll
    for (int c = 0; c < 32; c++) xv[c] = x[(size_t)(b*32 + c)*NN + p];
    if (q == 0) {
#pragma unroll
        for (int m = 0; m < 16; m++) {
            float a0 = 0.f, a1 = 0.f;
#pragma unroll
            for (int c = 0; c < 32; c++) {
                a0 += sw[(2*m)*32 + c]*xv[c];
                a1 += sw[(2*m+1)*32 + c]*xv[c];
            }
            g_cat96p16[(size_t)(b*48 + m)*NN + p] = pack_bf16x2(a0, a1);
        }
    } else {
        float mu = 0.f;
#pragma unroll
        for (int c = 0; c < 32; c++) mu += xv[c];
        mu *= (1.f/32.f);
        float var = 0.f;
#pragma unroll
        for (int c = 0; c < 32; c++) { float d = xv[c]-mu; var += d*d; }
        var *= (1.f/32.f);
        float inv = rsqrtf(var + 1e-5f);
        float vin[32];
#pragma unroll
        for (int c = 0; c < 32; c++) vin[c] = (xv[c]-mu)*inv*s_g[c] + s_b[c];
        float* outbase = g_qkv + (size_t)(b*96 + (q-1)*32)*NN;
        for (int o = 0; o < 32; o++) {
            float a = 0.f;
#pragma unroll
            for (int c = 0; c < 32; c++) a += sw[o*32+c]*vin[c];
            outbase[(size_t)o*NN + p] = a;
        }
    }
}

__device__ __forceinline__ void qkvd_body(float* ws, int blk, const float* __restrict__ w) {
    int tid = threadIdx.x;
    for (int i = tid; i < 96*27; i += 256) ws[i] = w[i];
    __syncthreads();
    int gid = blk*256 + tid;
    int p = gid % NN;
    int g = (gid / NN) % 32;
    int b = gid / (32*NN);
    int y = p >> 7, xx = p & 127;
    float a0 = 0.f, a1 = 0.f, a2 = 0.f;
    const float* inb = g_qkv + (size_t)(b*96 + 3*g)*NN;
#pragma unroll
    for (int ky = 0; ky < 3; ky++) {
        int gy = y - 1 + ky;
        if (gy < 0 || gy >= HH) continue;
#pragma unroll
        for (int kx = 0; kx < 3; kx++) {
            int gx = xx - 1 + kx;
            if (gx < 0 || gx >= WW) continue;
            int kk = ky*3 + kx;
#pragma unroll
            for (int ci = 0; ci < 3; ci++) {
                float v = inb[ci*NN + gy*WW + gx];
                a0 += ws[(3*g+0)*27 + ci*9 + kk]*v;
                a1 += ws[(3*g+1)*27 + ci*9 + kk]*v;
                a2 += ws[(3*g+2)*27 + ci*9 + kk]*v;
            }
        }
    }
    g_qkvd[(size_t)(b*96 + 3*g+0)*NN + p] = a0;
    g_qkvd[(size_t)(b*96 + 3*g+1)*NN + p] = a1;
    g_qkvd[(size_t)(b*96 + 3*g+2)*NN + p] = a2;
}

template<int MODE>
__device__ __forceinline__ void gramacc_body(float* red, int b, int h, int slice,
                                             const float* __restrict__ xin) {
    constexpr int D = (MODE == 0) ? 4 : 8;
    constexpr int E = 4;
    constexpr int NS = D*E + D + E;
    constexpr int SL = 16;
    int tid = threadIdx.x;
    const float* qbase;
    if (MODE == 0) qbase = g_qkvd + (size_t)(b*96 + h*D)*NN;
    else qbase = (h < 4) ? xin + (size_t)(b*32 + h*8)*NN
                         : g_prompt + (size_t)(b*32 + (h-4)*8)*NN;
    const float* kbase = (MODE == 0) ? g_qkvd + (size_t)(b*96 + 32 + h*E)*NN
                                     : g_kfeat + (size_t)(b*32 + h*E)*NN;
    float acc[NS];
#pragma unroll
    for (int i = 0; i < NS; i++) acc[i] = 0.f;
    int n0 = slice * (NN/SL);
    for (int it = 0; it < (NN/SL)/256; it++) {
        int n = n0 + it*256 + tid;
        float qv[D], kv[E];
#pragma unroll
        for (int d = 0; d < D; d++) qv[d] = qbase[(size_t)d*NN + n];
#pragma unroll
        for (int e = 0; e < E; e++) kv[e] = kbase[(size_t)e*NN + n];
#pragma unroll
        for (int d = 0; d < D; d++)
#pragma unroll
            for (int e = 0; e < E; e++) acc[d*E+e] += qv[d]*kv[e];
#pragma unroll
        for (int d = 0; d < D; d++) acc[D*E + d] += qv[d]*qv[d];
#pragma unroll
        for (int e = 0; e < E; e++) acc[D*E + D + e] += kv[e]*kv[e];
    }
    if (tid < NS) red[tid] = 0.f;
    __syncthreads();
    int lane = tid & 31;
#pragma unroll
    for (int i = 0; i < NS; i++) {
        float v = acc[i];
#pragma unroll
        for (int o = 16; o > 0; o >>= 1) v += __shfl_down_sync(0xffffffffu, v, o);
        if (lane == 0) atomicAdd(&red[i], v);
    }
    __syncthreads();
    float* st = (MODE == 0) ? g_stage_in + (b*8 + h)*24 : g_stage_f + (b*8 + h)*44;
    if (tid < NS) atomicAdd(&st[tid], red[tid]);
}

__device__ __forceinline__ void meffsm0_body(float* sA, int b,
        const float* __restrict__ wmat, const float* __restrict__ tempv) {
    int t = threadIdx.x;
    if (t < 32) {
        int h = t >> 2, d = t & 3;
        const float* st = g_stage_in + (b*8 + h)*24;
        float qn = fmaxf(sqrtf(st[16 + d]), 1e-12f);
        float tp = tempv[h];
        float row[4];
        float mx = -1e30f;
#pragma unroll
        for (int e = 0; e < 4; e++) {
            float kn = fmaxf(sqrtf(st[20 + e]), 1e-12f);
            row[e] = st[d*4+e] / (qn*kn) * tp;
            mx = fmaxf(mx, row[e]);
        }
        float sum = 0.f;
#pragma unroll
        for (int e = 0; e < 4; e++) { row[e] = expf(row[e]-mx); sum += row[e]; }
        float isum = 1.f/sum;
#pragma unroll
        for (int e = 0; e < 4; e++) sA[(h*4 + d)*4 + e] = row[e]*isum;
    }
    __syncthreads();
#pragma unroll
    for (int r = 0; r < 4; r++) {
        int idx = r*256 + t;
        int o = idx >> 5, vc = idx & 31, h = vc >> 2, e = vc & 3;
        float s = 0.f;
#pragma unroll
        for (int d = 0; d < 4; d++)
            s += wmat[o*32 + h*4 + d] * sA[(h*4 + d)*4 + e];
        g_Meff_in[b*1024 + o*32 + vc] = s;
    }
}

__global__ void k_meffsm1(const float* __restrict__ wmat, const float* __restrict__ tempv) {
    constexpr int D = 8;
    int b = blockIdx.x;
    int t = threadIdx.x;
    __shared__ float sA[8*D*4];
    if (t < 8*D) {
        int h = t / D, d = t % D;
        const float* st = g_stage_f + (b*8 + h)*44;
        float qn = fmaxf(sqrtf(st[D*4 + d]), 1e-12f);
        float tp = tempv[h];
        float row[4];
        float mx = -1e30f;
#pragma unroll
        for (int e = 0; e < 4; e++) {
            float kn = fmaxf(sqrtf(st[D*4 + D + e]), 1e-12f);
            row[e] = st[d*4+e] / (qn*kn) * tp;
            mx = fmaxf(mx, row[e]);
        }
        float sum = 0.f;
#pragma unroll
        for (int e = 0; e < 4; e++) { row[e] = expf(row[e]-mx); sum += row[e]; }
        float isum = 1.f/sum;
#pragma unroll
        for (int e = 0; e < 4; e++) sA[(h*D + d)*4 + e] = row[e]*isum;
    }
    __syncthreads();
    int o = t >> 5, vc = t & 31, h = vc >> 2, e = vc & 3;
    float s = 0.f;
#pragma unroll
    for (int d = 0; d < D; d++)
        s += wmat[o*(8*D) + h*D + d] * sA[(h*D + d)*4 + e];
    g_Meff_f[b*1024 + o*32 + vc] = s;
}

template<int MODE>
__device__ __forceinline__ void apply_body(float* sm, int blk,
        const float* __restrict__ xin, float* __restrict__ outp) {
    int tid = threadIdx.x;
    int gid = blk*256 + tid;
    int p = gid % NN;
    int q = (gid / NN) & 3;
    int b = gid / (4*NN);
    const float* M = (MODE == 0) ? g_Meff_in : g_Meff_f;
    if (tid < 256) sm[tid] = M[b*1024 + q*256 + tid];
    __syncthreads();
    float vv[32];
#pragma unroll
    for (int c = 0; c < 32; c++) {
        if (MODE == 0) vv[c] = g_qkvd[(size_t)(b*96 + 64 + c)*NN + p];
        else           vv[c] = xin[(size_t)(b*32 + c)*NN + p];
    }
    float av[8];
#pragma unroll
    for (int j = 0; j < 8; j++) {
        int o = q*8 + j;
        float a = (MODE == 0) ? xin[(size_t)(b*32 + o)*NN + p] : 0.f;
#pragma unroll
        for (int c = 0; c < 32; c++) a += sm[j*32+c]*vv[c];
        av[j] = a;
    }
    if (MODE == 0) {
#pragma unroll
        for (int m = 0; m < 4; m++)
            g_cat96p16[(size_t)(b*48 + 32 + q*4 + m)*NN + p] = pack_bf16x2(av[2*m], av[2*m+1]);
    } else {
#pragma unroll
        for (int j = 0; j < 8; j++)
            outp[(size_t)(b*32 + q*8 + j)*NN + p] = av[j];
    }
}

template<int K, int PAD>
__device__ __forceinline__ void deform_one(const float2* __restrict__ offp,
                                           const float* __restrict__ ws,
                                           const float* __restrict__ bsh,
                                           int yy, int xx, int b, int g, int p,
                                           int out0) {
    constexpr int K2 = K*K;
    float acc0 = 0.f, acc1 = 0.f, acc2 = 0.f, acc3 = 0.f;
    const float4* xb = g_xnhwc4 + (size_t)b*NN*8 + g;
    for (int k2 = 0; k2 < K2; k2++) {
        float2 d = offp[(size_t)k2*NN];
        float py = (float)(yy - PAD + k2 / K) + d.x;
        float px = (float)(xx - PAD + k2 % K) + d.y;
        float y0f = floorf(py), x0f = floorf(px);
        float wy = py - y0f, wx = px - x0f;
        int y0 = (int)y0f, x0 = (int)x0f;
        float w00 = (1.f-wy)*(1.f-wx), w01 = (1.f-wy)*wx, w10 = wy*(1.f-wx), w11 = wy*wx;
        bool iy0 = (y0 >= 0 && y0 < HH), iy1 = (y0+1 >= 0 && y0+1 < HH);
        bool ix0 = (x0 >= 0 && x0 < WW), ix1 = (x0+1 >= 0 && x0+1 < WW);
        float4 s = make_float4(0.f, 0.f, 0.f, 0.f);
        if (iy0 && ix0) {
            float4 v = xb[(size_t)(y0*WW + x0)*8];
            s.x += w00*v.x; s.y += w00*v.y; s.z += w00*v.z; s.w += w00*v.w;
        }
        if (iy0 && ix1) {
            float4 v = xb[(size_t)(y0*WW + x0 + 1)*8];
            s.x += w01*v.x; s.y += w01*v.y; s.z += w01*v.z; s.w += w01*v.w;
        }
        if (iy1 && ix0) {
            float4 v = xb[(size_t)((y0+1)*WW + x0)*8];
            s.x += w10*v.x; s.y += w10*v.y; s.z += w10*v.z; s.w += w10*v.w;
        }
        if (iy1 && ix1) {
            float4 v = xb[(size_t)((y0+1)*WW + x0 + 1)*8];
            s.x += w11*v.x; s.y += w11*v.y; s.z += w11*v.z; s.w += w11*v.w;
        }
        acc0 += ws[(0*4+0)*K2+k2]*s.x + ws[(0*4+1)*K2+k2]*s.y + ws[(0*4+2)*K2+k2]*s.z + ws[(0*4+3)*K2+k2]*s.w;
        acc1 += ws[(1*4+0)*K2+k2]*s.x + ws[(1*4+1)*K2+k2]*s.y + ws[(1*4+2)*K2+k2]*s.z + ws[(1*4+3)*K2+k2]*s.w;
        acc2 += ws[(2*4+0)*K2+k2]*s.x + ws[(2*4+1)*K2+k2]*s.y + ws[(2*4+2)*K2+k2]*s.z + ws[(2*4+3)*K2+k2]*s.w;
        acc3 += ws[(3*4+0)*K2+k2]*s.x + ws[(3*4+1)*K2+k2]*s.y + ws[(3*4+2)*K2+k2]*s.z + ws[(3*4+3)*K2+k2]*s.w;
    }
    float* ob = g_catf + (size_t)(b*96 + out0 + g*4)*NN + p;
    ob[0*NN] = fmaxf(acc0 + bsh[0], 0.f);
    ob[1*NN] = fmaxf(acc1 + bsh[1], 0.f);
    ob[2*NN] = fmaxf(acc2 + bsh[2], 0.f);
    ob[3*NN] = fmaxf(acc3 + bsh[3], 0.f);
}

__device__ __forceinline__ void deform_all_body(float* ws, int blk,
        const float* __restrict__ w3, const float* __restrict__ b3,
        const float* __restrict__ w5, const float* __restrict__ b5,
        const float* __restrict__ w7, const float* __restrict__ b7) {
    float* bsh = ws + 1328;
    int tid = threadIdx.x;
    int gid = blk*256 + tid;
    int p = gid % NN;
    int g = (gid / NN) & 7;
    int b = gid / (8*NN);
    for (int i = tid; i < 144; i += 256) ws[i] = w3[g*144 + i];
    for (int i = tid; i < 400; i += 256) ws[144 + i] = w5[g*400 + i];
    for (int i = tid; i < 784; i += 256) ws[544 + i] = w7[g*784 + i];
    if (tid < 4)       bsh[tid] = b3[g*4 + tid];
    else if (tid < 8)  bsh[tid] = b5[g*4 + tid - 4];
    else if (tid < 12) bsh[tid] = b7[g*4 + tid - 8];
    __syncthreads();
    int yy = p >> 7, xx = p & 127;
    const float2* offbase = g_offs2 + (size_t)(b*83)*NN + p;
    deform_one<3,1>(offbase,                 ws,     bsh,    yy, xx, b, g, p, 0);
    deform_one<5,2>(offbase + (size_t)9*NN,  ws+144, bsh+4,  yy, xx, b, g, p, 32);
    deform_one<7,3>(offbase + (size_t)34*NN, ws+544, bsh+8,  yy, xx, b, g, p, 64);
}

__device__ __forceinline__ void pw_body(float* ws, int blk,
        const float* __restrict__ w, const float* __restrict__ bias) {
    float* bs = ws + 768;
    int tid = threadIdx.x;
    int gid = blk*256 + tid;
    int p = gid % NN;
    int q = (gid / NN) & 3;
    int b = gid / (4*NN);
    for (int i = tid; i < 768; i += 256) ws[i] = w[(size_t)(q*8 + i/96)*96 + i%96];
    if (tid < 8) bs[tid] = bias[q*8 + tid];
    __syncthreads();
    float acc[8];
#pragma unroll
    for (int j = 0; j < 8; j++) acc[j] = bs[j];
    for (int c = 0; c < 96; c++) {
        float v = g_catf[(size_t)(b*96 + c)*NN + p];
#pragma unroll
        for (int j = 0; j < 8; j++) acc[j] += ws[j*96 + c]*v;
    }
#pragma unroll
    for (int j = 0; j < 8; j++) g_kfeat[(size_t)(b*32 + q*8 + j)*NN + p] = acc[j];
}

// ---------------- merged launch wrappers ----------------
// M1: [0,372) k2conv | [372,884) ln_l1_qkv | [884,1012) l2conv
__global__ void __launch_bounds__(256, 2) k_m1(const float* __restrict__ x,
        const float* __restrict__ ln_g, const float* __restrict__ ln_b,
        const float* __restrict__ w_lp1, const float* __restrict__ w_qkv) {
    __shared__ __align__(16) uint32_t sbuf[7168];
    int bid = blockIdx.x;
    if (bid < 372) {
        conv3x3_body<64,166,1, 2,32, 0,6, 0,166, 23040, 64,64,62,62, 0>(sbuf, sbuf + 4288, bid);
    } else if (bid < 884) {
        ln_l1_qkv_body((float*)sbuf, bid - 372, x, ln_g, ln_b, w_lp1, w_qkv);
    } else {
        conv3x3_body<32,32,0, 1,32, 1,4, 32,48, 0, 128,128,128,128, 1>(sbuf, sbuf + 4288, bid - 884);
    }
}

// M2: [0,768) k3conv | [768,1792) qkvd
__global__ void __launch_bounds__(256, 2) k_m2(const float* __restrict__ w_qkvd) {
    __shared__ __align__(16) uint32_t sbuf[7168];
    int bid = blockIdx.x;
    if (bid < 768) {
        conv3x3_body<64,166,2, 1,32, 1,3, 0,83, 92160, 128,128,128,128, 1>(sbuf, sbuf + 4288, bid);
    } else {
        qkvd_body((float*)sbuf, bid - 768, w_qkvd);
    }
}

// M3: [0,768) k4conv | [768,1024) gramacc0
__global__ void __launch_bounds__(256, 2) k_m3(const float* __restrict__ x) {
    __shared__ __align__(16) uint32_t sbuf[7168];
    int bid = blockIdx.x;
    if (bid < 768) {
        conv3x3_body<166,166,0, 3,83, 2,6, 0,83, 161280, 128,128,128,128, 1>(sbuf, sbuf + 4288, bid);
    } else {
        int i = bid - 768;
        gramacc_body<0>((float*)sbuf, i >> 7, (i >> 4) & 7, i & 15, x);
    }
}

// M4: [0,1024) deform | [1024,1026) meffsm0
__global__ void k_m4(const float* __restrict__ w3, const float* __restrict__ b3,
                     const float* __restrict__ w5, const float* __restrict__ b5,
                     const float* __restrict__ w7, const float* __restrict__ b7,
                     const float* __restrict__ w_mproj, const float* __restrict__ temp_in) {
    __shared__ float sf[1344];
    int bid = blockIdx.x;
    if (bid < 1024) {
        deform_all_body(sf, bid, w3, b3, w5, b5, w7, b7);
    } else {
        meffsm0_body(sf, bid - 1024, w_mproj, temp_in);
    }
}

// M5: [0,512) pw | [512,1024) apply0
__global__ void k_m5(const float* __restrict__ w_pw, const float* __restrict__ b_pw,
                     const float* __restrict__ x) {
    __shared__ float sf[800];
    int bid = blockIdx.x;
    if (bid < 512) {
        pw_body(sf, bid, w_pw, b_pw);
    } else {
        apply_body<0>(sf, bid - 512, x, nullptr);
    }
}

// M6: [0,128) c3conv | [128,256) gramacc1 with h<4 (x-half)
__global__ void __launch_bounds__(256, 2) k_m6(const float* __restrict__ x) {
    __shared__ __align__(16) uint32_t sbuf[7168];
    int bid = blockIdx.x;
    if (bid < 128) {
        conv3x3_body<96,32,0, 4,48, 0,11, 0,32, 5760, 128,128,128,128, 1>(sbuf, sbuf + 4288, bid);
    } else {
        int i = bid - 128;
        gramacc_body<1>((float*)sbuf, i >> 6, (i >> 4) & 3, i & 15, x);
    }
}

// M7: gramacc1 with h>=4 (prompt-half)
__global__ void k_m7(const float* __restrict__ x) {
    __shared__ float sf[64];
    int i = blockIdx.x;
    gramacc_body<1>(sf, i >> 6, 4 + ((i >> 4) & 3), i & 15, x);
}

// final apply
__global__ void k_apply1(const float* __restrict__ x, float* __restrict__ outp) {
    __shared__ float sf[256];
    apply_body<1>(sf, blockIdx.x, x, outp);
}

// ---------------- launch (kernel launches ONLY) ----------------
extern "C" void kernel_launch(void* const* d_in, const int* in_sizes, int n_in,
                              void* d_out, int out_size) {
    const float* x       = (const float*)d_in[0];
    const float* y       = (const float*)d_in[1];
    const float* temp    = (const float*)d_in[2];
    const float* w_po    = (const float*)d_in[3];
    const float* w_lp1   = (const float*)d_in[4];
    const float* w_lp2   = (const float*)d_in[5];
    const float* ln_g    = (const float*)d_in[6];
    const float* ln_b    = (const float*)d_in[7];
    const float* temp_in = (const float*)d_in[8];
    const float* w_qkv   = (const float*)d_in[9];
    const float* w_qkvd  = (const float*)d_in[10];
    const float* w_mproj = (const float*)d_in[11];
    const float* w_c3    = (const float*)d_in[12];
    const float* w_k2    = (const float*)d_in[13];
    const float* w_k3    = (const float*)d_in[14];
    const float* w_k4    = (const float*)d_in[15];
    const float* w_d3    = (const float*)d_in[16];
    const float* b_d3    = (const float*)d_in[17];
    const float* w_d5    = (const float*)d_in[18];
    const float* b_d5    = (const float*)d_in[19];
    const float* w_d7    = (const float*)d_in[20];
    const float* b_d7    = (const float*)d_in[21];
    const float* w_pw    = (const float*)d_in[22];
    const float* b_pw    = (const float*)d_in[23];

    k_setup<<<dim3(256, 8), 256>>>(x, y, w_lp2, w_c3, w_k2, w_k3, w_k4);  // 0
    k_m1<<<1012, 256>>>(x, ln_g, ln_b, w_lp1, w_qkv);                      // 1: k2 | ln+l1+qkv | l2
    k_m2<<<1792, 256>>>(w_qkvd);                                           // 2: k3 | qkvd
    k_m3<<<1024, 256>>>(x);                                                // 3: k4 | gramacc0  <- profiled
    k_m4<<<1026, 256>>>(w_d3, b_d3, w_d5, b_d5, w_d7, b_d7, w_mproj, temp_in); // 4
    k_m5<<<1024, 256>>>(w_pw, b_pw, x);                                    // 5: pw | apply0
    k_m6<<<256, 256>>>(x);                                                 // 6: c3 | gramacc1(h<4)
    k_m7<<<128, 256>>>(x);                                                 // 7: gramacc1(h>=4)
    k_meffsm1<<<BB, 1024>>>(w_po, temp);                                   // 8
    k_apply1<<<(BB*4*NN)/256, 256>>>(x, (float*)d_out);                    // 9
}